// round 2
// baseline (speedup 1.0000x reference)
#include <cuda_runtime.h>
#include <math.h>

#define B_  64
#define T_  512
#define C_  512
#define NTC (T_ * C_)          // 262144 elems per batch
#define TOT (B_ * T_ * C_)     // 16777216

// Scratch (allocation-free rule: __device__ globals)
__device__ float g_bufA[TOT];   // X1 (LN1 out), later reused as H (gelu out)
__device__ float g_Y[TOT];      // tri-mix + tri_b + residual
__device__ float g_X2[TOT];     // LN2 out
__device__ float g_stats[4 * B_]; // mu1[64], rs1[64], mu2[64], rs2[64]

// ---------------------------------------------------------------------------
// Per-batch mean / rstd over T*C elements. One block per batch.
// ---------------------------------------------------------------------------
__global__ void stats_kernel(const float* __restrict__ x,
                             float* __restrict__ mu, float* __restrict__ rs) {
    int b = blockIdx.x;
    const float4* p = (const float4*)(x + (size_t)b * NTC);
    float s = 0.f, s2 = 0.f;
    for (int i = threadIdx.x; i < NTC / 4; i += blockDim.x) {
        float4 v = p[i];
        s  += v.x + v.y + v.z + v.w;
        s2 += v.x * v.x + v.y * v.y + v.z * v.z + v.w * v.w;
    }
    __shared__ float sh[512];
    __shared__ float sh2[512];
    sh[threadIdx.x] = s;
    sh2[threadIdx.x] = s2;
    __syncthreads();
    for (int o = blockDim.x / 2; o > 0; o >>= 1) {
        if (threadIdx.x < o) {
            sh[threadIdx.x]  += sh[threadIdx.x + o];
            sh2[threadIdx.x] += sh2[threadIdx.x + o];
        }
        __syncthreads();
    }
    if (threadIdx.x == 0) {
        float m   = sh[0] / (float)NTC;
        float var = sh2[0] / (float)NTC - m * m;
        mu[b] = m;
        rs[b] = rsqrtf(var + 1e-5f);
    }
}

// ---------------------------------------------------------------------------
// out[b,t,c] = (x[b,t,c] - mu[b]) * rs[b] * w[t,c] + bias[t,c]
// ---------------------------------------------------------------------------
__global__ void ln_apply(const float* __restrict__ x,
                         const float* __restrict__ w,
                         const float* __restrict__ bias,
                         const float* __restrict__ mu,
                         const float* __restrict__ rs,
                         float* __restrict__ out) {
    int b = blockIdx.y;
    int idx = blockIdx.x * blockDim.x + threadIdx.x;   // float4 index in [0, NTC/4)
    float m = mu[b], r = rs[b];
    float4 xv = ((const float4*)(x + (size_t)b * NTC))[idx];
    float4 wv = ((const float4*)w)[idx];
    float4 bv = ((const float4*)bias)[idx];
    float4 o;
    o.x = (xv.x - m) * r * wv.x + bv.x;
    o.y = (xv.y - m) * r * wv.y + bv.y;
    o.z = (xv.z - m) * r * wv.z + bv.z;
    o.w = (xv.w - m) * r * wv.w + bv.w;
    ((float4*)(out + (size_t)b * NTC))[idx] = o;
}

// ---------------------------------------------------------------------------
// Dense NT GEMM: Out[m,n] = epilogue( sum_k A[m,k] * W[n,k] )
// 128x128 tile, BK=16, 256 threads, 8x8 micro-tile in 2x2 blocks of 4x4.
// EPI==1: gelu(acc + bias[n]);  EPI==2: acc + bias[n] + Res[m,n]
// ---------------------------------------------------------------------------
template <int EPI>
__global__ __launch_bounds__(256, 2)
void gemm128(const float* __restrict__ A, const float* __restrict__ W,
             const float* __restrict__ bias, const float* __restrict__ Res,
             float* __restrict__ Out, int M, int K, int N) {
    __shared__ float As[16][132];
    __shared__ float Bs[16][132];
    int tid = threadIdx.x;
    int m0 = blockIdx.y * 128;
    int n0 = blockIdx.x * 128;

    float acc[8][8];
#pragma unroll
    for (int i = 0; i < 8; i++)
#pragma unroll
        for (int j = 0; j < 8; j++) acc[i][j] = 0.f;

    int lr = tid >> 2;            // 0..63
    int lc = (tid & 3) * 4;       // 0,4,8,12
    const float* Ap = A + (size_t)(m0 + lr) * K + lc;
    const float* Wp = W + (size_t)(n0 + lr) * K + lc;

    int rm = (tid >> 4) * 4;      // 0..60
    int rn = (tid & 15) * 4;      // 0..60

    for (int k0 = 0; k0 < K; k0 += 16) {
        float4 a0 = *(const float4*)(Ap + k0);
        float4 a1 = *(const float4*)(Ap + (size_t)64 * K + k0);
        float4 b0 = *(const float4*)(Wp + k0);
        float4 b1 = *(const float4*)(Wp + (size_t)64 * K + k0);
        As[lc + 0][lr] = a0.x; As[lc + 1][lr] = a0.y; As[lc + 2][lr] = a0.z; As[lc + 3][lr] = a0.w;
        As[lc + 0][lr + 64] = a1.x; As[lc + 1][lr + 64] = a1.y; As[lc + 2][lr + 64] = a1.z; As[lc + 3][lr + 64] = a1.w;
        Bs[lc + 0][lr] = b0.x; Bs[lc + 1][lr] = b0.y; Bs[lc + 2][lr] = b0.z; Bs[lc + 3][lr] = b0.w;
        Bs[lc + 0][lr + 64] = b1.x; Bs[lc + 1][lr + 64] = b1.y; Bs[lc + 2][lr + 64] = b1.z; Bs[lc + 3][lr + 64] = b1.w;
        __syncthreads();
#pragma unroll
        for (int kk = 0; kk < 16; kk++) {
            float4 t0 = *(const float4*)&As[kk][rm];
            float4 t1 = *(const float4*)&As[kk][rm + 64];
            float4 u0 = *(const float4*)&Bs[kk][rn];
            float4 u1 = *(const float4*)&Bs[kk][rn + 64];
            float av[8] = {t0.x, t0.y, t0.z, t0.w, t1.x, t1.y, t1.z, t1.w};
            float bv[8] = {u0.x, u0.y, u0.z, u0.w, u1.x, u1.y, u1.z, u1.w};
#pragma unroll
            for (int i = 0; i < 8; i++)
#pragma unroll
                for (int j = 0; j < 8; j++)
                    acc[i][j] = fmaf(av[i], bv[j], acc[i][j]);
        }
        __syncthreads();
    }

    float4 bias0 = *(const float4*)&bias[n0 + rn];
    float4 bias1 = *(const float4*)&bias[n0 + rn + 64];
    float bb[8] = {bias0.x, bias0.y, bias0.z, bias0.w, bias1.x, bias1.y, bias1.z, bias1.w};

#pragma unroll
    for (int i = 0; i < 8; i++) {
        int gm = m0 + ((i < 4) ? (rm + i) : (rm + 64 + i - 4));
        float* orow = Out + (size_t)gm * N + n0;
        const float* rrow = (EPI == 2) ? (Res + (size_t)gm * N + n0) : nullptr;
#pragma unroll
        for (int half = 0; half < 2; half++) {
            int cb = rn + half * 64;
            float4 o;
            float v[4];
#pragma unroll
            for (int j = 0; j < 4; j++) {
                float t = acc[i][half * 4 + j] + bb[half * 4 + j];
                if (EPI == 1) {
                    t = 0.5f * t * (1.0f + erff(t * 0.70710678118654752f));
                }
                v[j] = t;
            }
            if (EPI == 2) {
                float4 rv = *(const float4*)(rrow + cb);
                v[0] += rv.x; v[1] += rv.y; v[2] += rv.z; v[3] += rv.w;
            }
            o.x = v[0]; o.y = v[1]; o.z = v[2]; o.w = v[3];
            *(float4*)(orow + cb) = o;
        }
    }
}

// ---------------------------------------------------------------------------
// Triangular time-mix batched GEMM:
// Y[b,i,c] = sum_{j<=i} M[i,j] * X1[b,j,c] + tri_b[i] + inputs[b,i,c]
// K-loop truncated at the diagonal tile; mask applied on M loads.
// ---------------------------------------------------------------------------
__global__ __launch_bounds__(256, 2)
void trigemm(const float* __restrict__ Mtri, const float* __restrict__ X1,
             const float* __restrict__ tb, const float* __restrict__ resid,
             float* __restrict__ Y) {
    __shared__ float As[16][132];
    __shared__ float Bs[16][132];
    int tid = threadIdx.x;
    int b  = blockIdx.z;
    int i0 = blockIdx.y * 128;
    int c0 = blockIdx.x * 128;
    const float* Xb = X1 + (size_t)b * NTC;
    const float* Rb = resid + (size_t)b * NTC;
    float* Yb = Y + (size_t)b * NTC;

    float acc[8][8];
#pragma unroll
    for (int i = 0; i < 8; i++)
#pragma unroll
        for (int j = 0; j < 8; j++) acc[i][j] = 0.f;

    int lr = tid >> 2;
    int lc = (tid & 3) * 4;
    const float* Ap = Mtri + (size_t)(i0 + lr) * T_ + lc;

    int brow = tid >> 5;          // 0..7
    int bcol = (tid & 31) * 4;    // 0..124

    int rm = (tid >> 4) * 4;
    int rn = (tid & 15) * 4;

    int kend = i0 + 128;          // upper tri tiles skipped entirely
    for (int k0 = 0; k0 < kend; k0 += 16) {
        // A tile (M) with tril mask
        float4 a0 = *(const float4*)(Ap + k0);
        float4 a1 = *(const float4*)(Ap + (size_t)64 * T_ + k0);
        int iA = i0 + lr, iB = i0 + lr + 64, jb = k0 + lc;
        As[lc + 0][lr] = (jb + 0 <= iA) ? a0.x : 0.f;
        As[lc + 1][lr] = (jb + 1 <= iA) ? a0.y : 0.f;
        As[lc + 2][lr] = (jb + 2 <= iA) ? a0.z : 0.f;
        As[lc + 3][lr] = (jb + 3 <= iA) ? a0.w : 0.f;
        As[lc + 0][lr + 64] = (jb + 0 <= iB) ? a1.x : 0.f;
        As[lc + 1][lr + 64] = (jb + 1 <= iB) ? a1.y : 0.f;
        As[lc + 2][lr + 64] = (jb + 2 <= iB) ? a1.z : 0.f;
        As[lc + 3][lr + 64] = (jb + 3 <= iB) ? a1.w : 0.f;
        // B tile (X1 rows j, cols c) — already [k][n] layout, direct copy
        float4 x0 = *(const float4*)(Xb + (size_t)(k0 + brow) * C_ + c0 + bcol);
        float4 x1 = *(const float4*)(Xb + (size_t)(k0 + brow + 8) * C_ + c0 + bcol);
        *(float4*)&Bs[brow][bcol] = x0;
        *(float4*)&Bs[brow + 8][bcol] = x1;
        __syncthreads();
#pragma unroll
        for (int kk = 0; kk < 16; kk++) {
            float4 t0 = *(const float4*)&As[kk][rm];
            float4 t1 = *(const float4*)&As[kk][rm + 64];
            float4 u0 = *(const float4*)&Bs[kk][rn];
            float4 u1 = *(const float4*)&Bs[kk][rn + 64];
            float av[8] = {t0.x, t0.y, t0.z, t0.w, t1.x, t1.y, t1.z, t1.w};
            float bv[8] = {u0.x, u0.y, u0.z, u0.w, u1.x, u1.y, u1.z, u1.w};
#pragma unroll
            for (int i = 0; i < 8; i++)
#pragma unroll
                for (int j = 0; j < 8; j++)
                    acc[i][j] = fmaf(av[i], bv[j], acc[i][j]);
        }
        __syncthreads();
    }

#pragma unroll
    for (int i = 0; i < 8; i++) {
        int gi = i0 + ((i < 4) ? (rm + i) : (rm + 64 + i - 4));
        float tbi = tb[gi];
        float* orow = Yb + (size_t)gi * C_ + c0;
        const float* rrow = Rb + (size_t)gi * C_ + c0;
#pragma unroll
        for (int half = 0; half < 2; half++) {
            int cb = rn + half * 64;
            float4 rv = *(const float4*)(rrow + cb);
            float4 o;
            o.x = acc[i][half * 4 + 0] + tbi + rv.x;
            o.y = acc[i][half * 4 + 1] + tbi + rv.y;
            o.z = acc[i][half * 4 + 2] + tbi + rv.z;
            o.w = acc[i][half * 4 + 3] + tbi + rv.w;
            *(float4*)(orow + cb) = o;
        }
    }
}

// ---------------------------------------------------------------------------
extern "C" void kernel_launch(void* const* d_in, const int* in_sizes, int n_in,
                              void* d_out, int out_size) {
    const float* inputs = (const float*)d_in[0];
    const float* ln1w   = (const float*)d_in[1];
    const float* ln1b   = (const float*)d_in[2];
    const float* ln2w   = (const float*)d_in[3];
    const float* ln2b   = (const float*)d_in[4];
    const float* triM   = (const float*)d_in[5];
    const float* trib   = (const float*)d_in[6];
    const float* d1w    = (const float*)d_in[7];
    const float* d1b    = (const float*)d_in[8];
    const float* d2w    = (const float*)d_in[9];
    const float* d2b    = (const float*)d_in[10];
    float* out = (float*)d_out;

    float *bufA, *Ybuf, *X2buf, *stats;
    cudaGetSymbolAddress((void**)&bufA,  g_bufA);
    cudaGetSymbolAddress((void**)&Ybuf,  g_Y);
    cudaGetSymbolAddress((void**)&X2buf, g_X2);
    cudaGetSymbolAddress((void**)&stats, g_stats);
    float* mu1 = stats;
    float* rs1 = stats + B_;
    float* mu2 = stats + 2 * B_;
    float* rs2 = stats + 3 * B_;

    dim3 lnGrid(NTC / 4 / 256, B_);

    // 1) per-batch stats of inputs
    stats_kernel<<<B_, 512>>>(inputs, mu1, rs1);
    // 2) X1 = LN1(inputs)
    ln_apply<<<lnGrid, 256>>>(inputs, ln1w, ln1b, mu1, rs1, bufA);
    // 3) Y = tril(M) @ X1 + tri_b + inputs
    trigemm<<<dim3(C_ / 128, T_ / 128, B_), 256>>>(triM, bufA, trib, inputs, Ybuf);
    // 4) per-batch stats of Y
    stats_kernel<<<B_, 512>>>(Ybuf, mu2, rs2);
    // 5) X2 = LN2(Y)
    ln_apply<<<lnGrid, 256>>>(Ybuf, ln2w, ln2b, mu2, rs2, X2buf);
    // 6) H = gelu(X2 @ d1_w^T + d1_b)   (bufA reused as H)
    gemm128<1><<<dim3(C_ / 128, (B_ * T_) / 128), 256>>>(X2buf, d1w, d1b, nullptr, bufA,
                                                          B_ * T_, C_, C_);
    // 7) out = X2 + H @ d2_w^T + d2_b
    gemm128<2><<<dim3(C_ / 128, (B_ * T_) / 128), 256>>>(bufA, d2w, d2b, X2buf, out,
                                                          B_ * T_, C_, C_);
}